// round 15
// baseline (speedup 1.0000x reference)
#include <cuda_runtime.h>
#include <math.h>

#define NN 100000
#define EE 1000000
#define FIN 500
#define HH 64
#define HB 128
#define CC 3
#define EPS_MSG 1e-7f
#define LN_EPS  1e-5f

typedef unsigned int u32;

// ---------------- device scratch ----------------
static __device__ float g_h [(size_t)NN*HH];
static __device__ float g_hB[(size_t)NN*HH];
static __device__ int   g_rowptr[NN+1];
static __device__ int   g_fill[NN];
static __device__ int   g_scan[NN];
static __device__ int   g_esrc[EE];
static __device__ int   g_bsums[128];
static __device__ int   g_is64;
// pre-scattered B fragments, rna-rounded tf32 (enc padded to 64 kb-blocks)
static __device__ u32   g_encBf[32768];
static __device__ u32   g_W1f[3*8192];
static __device__ u32   g_W2f[3*8192];

// ---------------- helpers ----------------
__device__ __forceinline__ u32 tf32_rna(float f){
  u32 u; asm("cvt.rna.tf32.f32 %0, %1;" : "=r"(u) : "f"(f)); return u;
}
__device__ __forceinline__ void mma8(float* d, u32 a0,u32 a1,u32 a2,u32 a3,u32 b0,u32 b1){
  asm volatile("mma.sync.aligned.m16n8k8.row.col.f32.tf32.tf32.f32 "
   "{%0,%1,%2,%3},{%4,%5,%6,%7},{%8,%9},{%0,%1,%2,%3};"
   : "+f"(d[0]),"+f"(d[1]),"+f"(d[2]),"+f"(d[3])
   : "r"(a0),"r"(a1),"r"(a2),"r"(a3),"r"(b0),"r"(b1));
}
__device__ __forceinline__ u32 smem_u32(const void* p){
  u32 a; asm("{ .reg .u64 t; cvta.to.shared.u64 t, %1; cvt.u32.u64 %0, t; }" : "=r"(a) : "l"(p)); return a;
}
__device__ __forceinline__ void cp16(u32 dst, const void* src, int bytes){
  asm volatile("cp.async.ca.shared.global [%0], [%1], 16, %2;"
    :: "r"(dst), "l"(src), "r"(bytes) : "memory");
}

// 2-chain step: acc += (Ahi + Alo) * B
#define SPLIT_A(f0,f1,f2,f3) \
  u32 ah0=tf32_rna(f0), ah1=tf32_rna(f1), ah2=tf32_rna(f2), ah3=tf32_rna(f3); \
  u32 al0=__float_as_uint((f0)-__uint_as_float(ah0)); \
  u32 al1=__float_as_uint((f1)-__uint_as_float(ah1)); \
  u32 al2=__float_as_uint((f2)-__uint_as_float(ah2)); \
  u32 al3=__float_as_uint((f3)-__uint_as_float(ah3));

// ---------------- edge dtype detection / CSR ----------------
__global__ void k_detect(const void* ei){
  if(blockIdx.x==0 && threadIdx.x==0){
    const long long* p=(const long long*)ei;
    int ok=1;
    #pragma unroll
    for(int i=0;i<8;i++){ long long v=p[i]; if(v<0||v>=NN) ok=0; }
    g_is64=ok;
  }
}
__device__ __forceinline__ int edge_src(const void* ei,int e){
  return g_is64 ? (int)((const long long*)ei)[e] : ((const int*)ei)[e];
}
__device__ __forceinline__ int edge_dst(const void* ei,int e){
  return g_is64 ? (int)((const long long*)ei)[EE+e] : ((const int*)ei)[EE+e];
}
__global__ void k_zero(){
  int i=blockIdx.x*blockDim.x+threadIdx.x;
  if(i<NN) g_fill[i]=0;
}
__global__ void k_hist(const void* ei){
  int e=blockIdx.x*blockDim.x+threadIdx.x;
  if(e>=EE) return;
  atomicAdd(&g_fill[edge_dst(ei,e)],1);
}
__device__ __forceinline__ int block_incl_scan(int v){
  int lane=threadIdx.x&31, wid=threadIdx.x>>5;
  int x=v;
  #pragma unroll
  for(int o=1;o<32;o<<=1){ int y=__shfl_up_sync(0xffffffffu,x,o); if(lane>=o) x+=y; }
  __shared__ int ws[32];
  if(lane==31) ws[wid]=x;
  __syncthreads();
  int nw=(blockDim.x+31)>>5;
  if(wid==0){
    int y=(lane<nw)? ws[lane]:0;
    #pragma unroll
    for(int o=1;o<32;o<<=1){ int z=__shfl_up_sync(0xffffffffu,y,o); if(lane>=o) y+=z; }
    ws[lane]=y;
  }
  __syncthreads();
  return x + (wid>0? ws[wid-1]:0);
}
__global__ void k_scan1(){
  int i=blockIdx.x*1024+threadIdx.x;
  int v=(i<NN)? g_fill[i]:0;
  int incl=block_incl_scan(v);
  if(i<NN) g_scan[i]=incl;
  if(threadIdx.x==1023) g_bsums[blockIdx.x]=incl;
}
__global__ void k_scan2(){
  int t=threadIdx.x;
  int v=(t<98)? g_bsums[t]:0;
  int incl=block_incl_scan(v);
  if(t<98) g_bsums[t]=incl-v;
}
__global__ void k_scan3(){
  int i=blockIdx.x*blockDim.x+threadIdx.x;
  if(i>=NN) return;
  int c=g_fill[i];
  int incl=g_scan[i]+g_bsums[i>>10];
  g_rowptr[i+1]=incl;
  g_fill[i]=incl-c;
  if(i==0) g_rowptr[0]=0;
}
__global__ void k_scatter(const void* ei){
  int e=blockIdx.x*blockDim.x+threadIdx.x;
  if(e>=EE) return;
  int s=edge_src(ei,e);
  int d=edge_dst(ei,e);
  int pos=atomicAdd(&g_fill[d],1);
  g_esrc[pos]=s;
}

// ---------------- B-fragment prep (rna single block) ----------------
__global__ void k_prep(const float* __restrict__ encW,
                       const float* __restrict__ W1,
                       const float* __restrict__ W2){
  int idx=blockIdx.x*blockDim.x+threadIdx.x;
  if(idx<32768){                 // enc: 512 k x 64 n (zeros past 500), NB=8
    int k=idx>>6, n=idx&63;
    float v=(k<FIN)? encW[(size_t)k*HH+n] : 0.f;
    int kb=k>>3, kw=k&7;
    g_encBf[(((kb*8)+(n>>3))*32 + ((n&7)*4+(kw&3)))*2 + (kw>>2)]=tf32_rna(v);
  }else if(idx<32768+3*8192){    // W1: 64 k x 128 n, NB=16
    int j=idx-32768;
    int l=j>>13, e=j&8191;
    int k=e>>7, n=e&127;
    float v=W1[(size_t)l*64*128 + (size_t)k*HB + n];
    int kb=k>>3, kw=k&7;
    g_W1f[l*8192 + (((kb*16)+(n>>3))*32 + ((n&7)*4+(kw&3)))*2 + (kw>>2)]=tf32_rna(v);
  }else if(idx<32768+6*8192){    // W2: 128 k x 64 n, NB=8
    int j=idx-32768-3*8192;
    int l=j>>13, e=j&8191;
    int k=e>>6, n=e&63;
    float v=W2[(size_t)l*128*64 + (size_t)k*HH + n];
    int kb=k>>3, kw=k&7;
    g_W2f[l*8192 + (((kb*8)+(n>>3))*32 + ((n&7)*4+(kw&3)))*2 + (kw>>2)]=tf32_rna(v);
  }
}

// ---------------- encoder GEMM: cp.async double-buffered, 8 stages of 64 k ----------------
#define EPITCH 68
__global__ void __launch_bounds__(256) k_enc(const float* __restrict__ x,
                                             const float* __restrict__ bias){
  __shared__ float sbuf[2][128*EPITCH];
  const int tid=threadIdx.x, lane=tid&31, wid=tid>>5;
  const int g=lane>>2, qc=lane&3;
  const int r0=blockIdx.x*128 + wid*16 + g;
  float acc[8][4];
  #pragma unroll
  for(int nb=0;nb<8;nb++)
    #pragma unroll
    for(int j=0;j<4;j++) acc[nb][j]=0.f;

  const u32 sb0=smem_u32(&sbuf[0][0]);
  const u32 sb1=smem_u32(&sbuf[1][0]);
  const uint2* bp=((const uint2*)g_encBf)+lane;

  // issue one 64-k stage (128 rows x 64 floats = 2048 x 16B; 8 per thread)
  #define ISSUE(c) do{ \
    u32 dbase=((c)&1)? sb1:sb0; \
    _Pragma("unroll") \
    for(int rep=0;rep<8;rep++){ \
      int idx=tid+rep*256; \
      int row=idx>>4, seg=idx&15; \
      int gr=min(blockIdx.x*128+row, NN-1); \
      int kk=(c)*64+seg*4; \
      int kkc=min(kk,FIN-4); \
      int rem=(FIN-kk)*4; \
      int bytes=rem>=16?16:(rem>0?rem:0); \
      cp16(dbase+(u32)(row*EPITCH+seg*4)*4u, x+(size_t)gr*FIN+kkc, bytes); \
    } \
    asm volatile("cp.async.commit_group;":::"memory"); \
  }while(0)

  ISSUE(0);
  for(int c=0;c<8;c++){
    if(c<7){
      ISSUE(c+1);
      asm volatile("cp.async.wait_group 1;":::"memory");
    }else{
      asm volatile("cp.async.wait_group 0;":::"memory");
    }
    __syncthreads();
    const float* sb=((c&1)? &sbuf[1][0] : &sbuf[0][0]);
    const int ra=(wid*16+g)*EPITCH, rb=(wid*16+g+8)*EPITCH;
    #pragma unroll
    for(int s=0;s<8;s++){
      int k0=s*8+qc;
      float f0=sb[ra+k0];
      float f1=sb[rb+k0];
      float f2=sb[ra+k0+4];
      float f3=sb[rb+k0+4];
      SPLIT_A(f0,f1,f2,f3)
      const uint2* bk=bp+(size_t)(c*8+s)*8*32;
      #pragma unroll
      for(int nb=0;nb<8;nb++){
        uint2 bh=__ldg(bk+nb*32);
        mma8(acc[nb],ah0,ah1,ah2,ah3,bh.x,bh.y);
        mma8(acc[nb],al0,al1,al2,al3,bh.x,bh.y);
      }
    }
    __syncthreads();
  }
  #pragma unroll
  for(int nb=0;nb<8;nb++){
    int col=nb*8+qc*2;
    float b0v=__ldg(bias+col), b1v=__ldg(bias+col+1);
    if(r0<NN)   *(float2*)(g_h+(size_t)r0*HH+col)    =make_float2(acc[nb][0]+b0v,acc[nb][1]+b1v);
    if(r0+8<NN) *(float2*)(g_h+(size_t)(r0+8)*HH+col)=make_float2(acc[nb][2]+b0v,acc[nb][3]+b1v);
  }
}

// ---------------- fused conv: agg -> smem A -> gemm1+LN -> smem h1 -> gemm2 ----------------
// MODE 0: hout = gemm2+b2               (pre-loop conv)
// MODE 1: hout = hin + relu(LN(gemm2+b2, gma,bet))
// MODE 2: MODE1 epilogue fused with final: out = relu(LN(hnew, fng,fnb)) @ linW + linB
// bufsel 0: hin=g_h, hout=g_hB ; bufsel 1: hin=g_hB, hout=g_h
#define SPITCH 132
#define APITCH 68
template<int MODE>
__global__ void __launch_bounds__(256) k_conv(const float* __restrict__ tptr,
                       int boff, int bufsel,
                       const float* __restrict__ b1v,
                       const float* __restrict__ g1v,
                       const float* __restrict__ be1v,
                       const float* __restrict__ b2v,
                       const float* __restrict__ gmav,
                       const float* __restrict__ betv,
                       const float* __restrict__ fng,
                       const float* __restrict__ fnb,
                       const float* __restrict__ linW,
                       const float* __restrict__ linB,
                       float* __restrict__ out){
  extern __shared__ float sh[];
  const float* hin = bufsel? g_hB : g_h;
  float*       hout= bufsel? g_h  : g_hB;
  const int tid=threadIdx.x, lane=tid&31, wid=tid>>5;
  const int g=lane>>2, qc=lane&3;
  const int lr0=wid*16+g;
  const int r0=blockIdx.x*128 + lr0;

  // ---- stage 0: aggregation directly into A smem (warp handles 16 nodes) ----
  {
    float tv=*tptr;
    for(int i=0;i<16;i++){
      int lr=wid*16+i;
      int nc=min(blockIdx.x*128+lr, NN-1);
      int s0=g_rowptr[nc], s1=g_rowptr[nc+1];
      float den0=0.f,den1=0.f,num0=0.f,num1=0.f;
      for(int base=s0;base<s1;base+=32){
        int cnt=min(32,s1-base);
        int idx=(base+lane<s1)? g_esrc[base+lane]:0;
        for(int j=0;j<cnt;j++){
          int s=__shfl_sync(0xffffffffu,idx,j);
          float2 v=*(const float2*)(hin+(size_t)s*HH+2*lane);
          float m0=fmaxf(v.x,0.f)+EPS_MSG;
          float m1=fmaxf(v.y,0.f)+EPS_MSG;
          float a0=__expf(m0*tv);
          float a1=__expf(m1*tv);
          den0+=a0; den1+=a1;
          num0=fmaf(m0,a0,num0);
          num1=fmaf(m1,a1,num1);
        }
      }
      float2 hv=*(const float2*)(hin+(size_t)nc*HH+2*lane);
      float o0=(s1>s0)? num0/den0:0.f;
      float o1=(s1>s0)? num1/den1:0.f;
      sh[lr*APITCH+2*lane  ]=o0+hv.x;
      sh[lr*APITCH+2*lane+1]=o1+hv.y;
    }
  }
  __syncthreads();

  // ---- gemm1: 128x128 = A(128x64) @ W1, NB=16, KBN=8, A from smem ----
  float h1acc[16][4];
  {
    #pragma unroll
    for(int nb=0;nb<16;nb++)
      #pragma unroll
      for(int j=0;j<4;j++) h1acc[nb][j]=0.f;
    const uint2* bp=((const uint2*)(g_W1f+boff))+lane;
    const int ra=lr0*APITCH, rb=(lr0+8)*APITCH;
    #pragma unroll
    for(int kb=0;kb<8;kb++){
      int k0=kb*8+qc;
      float f0=sh[ra+k0];
      float f1=sh[rb+k0];
      float f2=sh[ra+k0+4];
      float f3=sh[rb+k0+4];
      SPLIT_A(f0,f1,f2,f3)
      const uint2* bk=bp+(size_t)kb*16*32;
      #pragma unroll
      for(int nb=0;nb<16;nb++){
        uint2 bh=__ldg(bk+nb*32);
        mma8(h1acc[nb],ah0,ah1,ah2,ah3,bh.x,bh.y);
        mma8(h1acc[nb],al0,al1,al2,al3,bh.x,bh.y);
      }
    }
  }
  __syncthreads();   // all warps done reading staged A before overwriting sh with h1

  {
    float s0=0.f,ss0=0.f,s1=0.f,ss1=0.f;
    #pragma unroll
    for(int nb=0;nb<16;nb++){
      int col=nb*8+qc*2;
      float c0=__ldg(b1v+col), c1=__ldg(b1v+col+1);
      h1acc[nb][0]+=c0; h1acc[nb][1]+=c1; h1acc[nb][2]+=c0; h1acc[nb][3]+=c1;
      s0+=h1acc[nb][0]+h1acc[nb][1]; ss0+=h1acc[nb][0]*h1acc[nb][0]+h1acc[nb][1]*h1acc[nb][1];
      s1+=h1acc[nb][2]+h1acc[nb][3]; ss1+=h1acc[nb][2]*h1acc[nb][2]+h1acc[nb][3]*h1acc[nb][3];
    }
    #pragma unroll
    for(int o=1;o<4;o<<=1){
      s0 +=__shfl_xor_sync(0xffffffffu,s0 ,o);
      ss0+=__shfl_xor_sync(0xffffffffu,ss0,o);
      s1 +=__shfl_xor_sync(0xffffffffu,s1 ,o);
      ss1+=__shfl_xor_sync(0xffffffffu,ss1,o);
    }
    float mu0=s0*(1.f/128.f), mu1=s1*(1.f/128.f);
    float rs0=rsqrtf(ss0*(1.f/128.f)-mu0*mu0+LN_EPS);
    float rs1=rsqrtf(ss1*(1.f/128.f)-mu1*mu1+LN_EPS);
    #pragma unroll
    for(int nb=0;nb<16;nb++){
      int col=nb*8+qc*2;
      float gv0=__ldg(g1v+col), gv1=__ldg(g1v+col+1);
      float ev0=__ldg(be1v+col), ev1=__ldg(be1v+col+1);
      sh[lr0*SPITCH+col  ]   =fmaxf((h1acc[nb][0]-mu0)*rs0*gv0+ev0,0.f);
      sh[lr0*SPITCH+col+1]   =fmaxf((h1acc[nb][1]-mu0)*rs0*gv1+ev1,0.f);
      sh[(lr0+8)*SPITCH+col  ]=fmaxf((h1acc[nb][2]-mu1)*rs1*gv0+ev0,0.f);
      sh[(lr0+8)*SPITCH+col+1]=fmaxf((h1acc[nb][3]-mu1)*rs1*gv1+ev1,0.f);
    }
  }
  __syncwarp();

  // ---- gemm2: 128x64 = h1(128x128) @ W2, NB=8, KBN=16, A from smem ----
  float acc[8][4];
  #pragma unroll
  for(int nb=0;nb<8;nb++)
    #pragma unroll
    for(int j=0;j<4;j++) acc[nb][j]=0.f;
  const uint2* bp2=((const uint2*)(g_W2f+boff))+lane;
  #pragma unroll
  for(int kb=0;kb<16;kb++){
    int k0=kb*8+qc;
    float f0=sh[lr0*SPITCH+k0];
    float f1=sh[(lr0+8)*SPITCH+k0];
    float f2=sh[lr0*SPITCH+k0+4];
    float f3=sh[(lr0+8)*SPITCH+k0+4];
    SPLIT_A(f0,f1,f2,f3)
    const uint2* bk=bp2+(size_t)kb*8*32;
    #pragma unroll
    for(int nb=0;nb<8;nb++){
      uint2 bh=__ldg(bk+nb*32);
      mma8(acc[nb],ah0,ah1,ah2,ah3,bh.x,bh.y);
      mma8(acc[nb],al0,al1,al2,al3,bh.x,bh.y);
    }
  }

  if(MODE==0){
    #pragma unroll
    for(int nb=0;nb<8;nb++){
      int col=nb*8+qc*2;
      float c0=__ldg(b2v+col), c1=__ldg(b2v+col+1);
      if(r0<NN)   *(float2*)(hout+(size_t)r0*HH+col)    =make_float2(acc[nb][0]+c0,acc[nb][1]+c1);
      if(r0+8<NN) *(float2*)(hout+(size_t)(r0+8)*HH+col)=make_float2(acc[nb][2]+c0,acc[nb][3]+c1);
    }
  }else{
    // residual LN over 64 cols
    float s0=0.f,ss0=0.f,s1=0.f,ss1=0.f;
    #pragma unroll
    for(int nb=0;nb<8;nb++){
      int col=nb*8+qc*2;
      float c0=__ldg(b2v+col), c1=__ldg(b2v+col+1);
      acc[nb][0]+=c0; acc[nb][1]+=c1; acc[nb][2]+=c0; acc[nb][3]+=c1;
      s0+=acc[nb][0]+acc[nb][1]; ss0+=acc[nb][0]*acc[nb][0]+acc[nb][1]*acc[nb][1];
      s1+=acc[nb][2]+acc[nb][3]; ss1+=acc[nb][2]*acc[nb][2]+acc[nb][3]*acc[nb][3];
    }
    #pragma unroll
    for(int o=1;o<4;o<<=1){
      s0 +=__shfl_xor_sync(0xffffffffu,s0 ,o);
      ss0+=__shfl_xor_sync(0xffffffffu,ss0,o);
      s1 +=__shfl_xor_sync(0xffffffffu,s1 ,o);
      ss1+=__shfl_xor_sync(0xffffffffu,ss1,o);
    }
    float mu0=s0*(1.f/64.f), mu1=s1*(1.f/64.f);
    float rs0=rsqrtf(ss0*(1.f/64.f)-mu0*mu0+LN_EPS);
    float rs1=rsqrtf(ss1*(1.f/64.f)-mu1*mu1+LN_EPS);
    // hnew = hin + relu(LN(..)) kept in acc
    float fs0=0.f,fss0=0.f,fs1=0.f,fss1=0.f;
    #pragma unroll
    for(int nb=0;nb<8;nb++){
      int col=nb*8+qc*2;
      float gv0=__ldg(gmav+col), gv1=__ldg(gmav+col+1);
      float ev0=__ldg(betv+col), ev1=__ldg(betv+col+1);
      float o0=fmaxf((acc[nb][0]-mu0)*rs0*gv0+ev0,0.f);
      float o1=fmaxf((acc[nb][1]-mu0)*rs0*gv1+ev1,0.f);
      float o2=fmaxf((acc[nb][2]-mu1)*rs1*gv0+ev0,0.f);
      float o3=fmaxf((acc[nb][3]-mu1)*rs1*gv1+ev1,0.f);
      int rc0=min(r0,NN-1), rc1=min(r0+8,NN-1);
      float2 old0=*(const float2*)(hin+(size_t)rc0*HH+col);
      float2 old1=*(const float2*)(hin+(size_t)rc1*HH+col);
      acc[nb][0]=old0.x+o0; acc[nb][1]=old0.y+o1;
      acc[nb][2]=old1.x+o2; acc[nb][3]=old1.y+o3;
      if(MODE==1){
        if(r0<NN)   *(float2*)(hout+(size_t)r0*HH+col)    =make_float2(acc[nb][0],acc[nb][1]);
        if(r0+8<NN) *(float2*)(hout+(size_t)(r0+8)*HH+col)=make_float2(acc[nb][2],acc[nb][3]);
      }else{
        fs0+=acc[nb][0]+acc[nb][1]; fss0+=acc[nb][0]*acc[nb][0]+acc[nb][1]*acc[nb][1];
        fs1+=acc[nb][2]+acc[nb][3]; fss1+=acc[nb][2]*acc[nb][2]+acc[nb][3]*acc[nb][3];
      }
    }
    if(MODE==2){
      #pragma unroll
      for(int o=1;o<4;o<<=1){
        fs0 +=__shfl_xor_sync(0xffffffffu,fs0 ,o);
        fss0+=__shfl_xor_sync(0xffffffffu,fss0,o);
        fs1 +=__shfl_xor_sync(0xffffffffu,fs1 ,o);
        fss1+=__shfl_xor_sync(0xffffffffu,fss1,o);
      }
      float fmu0=fs0*(1.f/64.f), fmu1=fs1*(1.f/64.f);
      float frs0=rsqrtf(fss0*(1.f/64.f)-fmu0*fmu0+LN_EPS);
      float frs1=rsqrtf(fss1*(1.f/64.f)-fmu1*fmu1+LN_EPS);
      float p00=0.f,p01=0.f,p02=0.f,p10=0.f,p11=0.f,p12=0.f;
      #pragma unroll
      for(int nb=0;nb<8;nb++){
        int col=nb*8+qc*2;
        float n0=__ldg(fng+col), n1=__ldg(fng+col+1);
        float e0=__ldg(fnb+col), e1=__ldg(fnb+col+1);
        float r00=fmaxf((acc[nb][0]-fmu0)*frs0*n0+e0,0.f);
        float r01=fmaxf((acc[nb][1]-fmu0)*frs0*n1+e1,0.f);
        float r10=fmaxf((acc[nb][2]-fmu1)*frs1*n0+e0,0.f);
        float r11=fmaxf((acc[nb][3]-fmu1)*frs1*n1+e1,0.f);
        float w00=__ldg(linW+col*CC+0), w01=__ldg(linW+col*CC+1), w02=__ldg(linW+col*CC+2);
        float w10=__ldg(linW+(col+1)*CC+0), w11=__ldg(linW+(col+1)*CC+1), w12=__ldg(linW+(col+1)*CC+2);
        p00+=r00*w00+r01*w10; p01+=r00*w01+r01*w11; p02+=r00*w02+r01*w12;
        p10+=r10*w00+r11*w10; p11+=r10*w01+r11*w11; p12+=r10*w02+r11*w12;
      }
      #pragma unroll
      for(int o=1;o<4;o<<=1){
        p00+=__shfl_xor_sync(0xffffffffu,p00,o);
        p01+=__shfl_xor_sync(0xffffffffu,p01,o);
        p02+=__shfl_xor_sync(0xffffffffu,p02,o);
        p10+=__shfl_xor_sync(0xffffffffu,p10,o);
        p11+=__shfl_xor_sync(0xffffffffu,p11,o);
        p12+=__shfl_xor_sync(0xffffffffu,p12,o);
      }
      if(qc==0){
        float lb0=__ldg(linB+0), lb1=__ldg(linB+1), lb2=__ldg(linB+2);
        if(r0<NN){
          out[(size_t)r0*CC+0]=p00+lb0;
          out[(size_t)r0*CC+1]=p01+lb1;
          out[(size_t)r0*CC+2]=p02+lb2;
        }
        if(r0+8<NN){
          out[(size_t)(r0+8)*CC+0]=p10+lb0;
          out[(size_t)(r0+8)*CC+1]=p11+lb1;
          out[(size_t)(r0+8)*CC+2]=p12+lb2;
        }
      }
    }
  }
}

// ---------------- launch ----------------
extern "C" void kernel_launch(void* const* d_in, const int* in_sizes, int n_in,
                              void* d_out, int out_size){
  const float* x    =(const float*)d_in[0];
  const void * ei   =              d_in[1];
  const float* encW =(const float*)d_in[2];
  const float* encB =(const float*)d_in[3];
  const float* W1   =(const float*)d_in[4];
  const float* b1   =(const float*)d_in[5];
  const float* g1   =(const float*)d_in[6];
  const float* be1  =(const float*)d_in[7];
  const float* W2   =(const float*)d_in[8];
  const float* b2   =(const float*)d_in[9];
  const float* t    =(const float*)d_in[10];
  const float* ng   =(const float*)d_in[11];
  const float* nb   =(const float*)d_in[12];
  const float* linW =(const float*)d_in[13];
  const float* linB =(const float*)d_in[14];
  float* out=(float*)d_out;

  const int G=(NN+127)/128;        // 782
  const int SM_CONV=128*SPITCH*4;  // 67584 B

  cudaFuncSetAttribute(k_conv<0>, cudaFuncAttributeMaxDynamicSharedMemorySize, SM_CONV);
  cudaFuncSetAttribute(k_conv<1>, cudaFuncAttributeMaxDynamicSharedMemorySize, SM_CONV);
  cudaFuncSetAttribute(k_conv<2>, cudaFuncAttributeMaxDynamicSharedMemorySize, SM_CONV);

  k_prep  <<<(32768+6*8192+255)/256,256>>>(encW,W1,W2);        // 0
  k_detect<<<1,32>>>(ei);                                      // 1
  k_zero  <<<(NN+255)/256,256>>>();                            // 2
  k_enc   <<<G,256>>>(x,encB);                                 // 3: profiled slot
  k_hist  <<<(EE+511)/512,512>>>(ei);
  k_scan1 <<<98,1024>>>();
  k_scan2 <<<1,128>>>();
  k_scan3 <<<(NN+255)/256,256>>>();
  k_scatter<<<(EE+511)/512,512>>>(ei);

  // pre-loop conv (layer 0 params): g_h -> g_hB
  k_conv<0><<<G,256,SM_CONV>>>(t+0, 0, 0, b1,g1,be1, b2, ng,nb, ng,nb, linW,linB, out);
  // layer 0: g_hB -> g_h
  k_conv<1><<<G,256,SM_CONV>>>(t+0, 0, 1, b1,g1,be1, b2, ng,nb, ng,nb, linW,linB, out);
  // layer 1: g_h -> g_hB
  k_conv<1><<<G,256,SM_CONV>>>(t+1, 1*8192, 0,
                               b1+(size_t)1*HB, g1+(size_t)1*HB, be1+(size_t)1*HB,
                               b2+(size_t)1*HH, ng+(size_t)1*HH, nb+(size_t)1*HH,
                               ng,nb, linW,linB, out);
  // layer 2 (final fused): g_hB -> out
  k_conv<2><<<G,256,SM_CONV>>>(t+2, 2*8192, 1,
                               b1+(size_t)2*HB, g1+(size_t)2*HB, be1+(size_t)2*HB,
                               b2+(size_t)2*HH, ng+(size_t)2*HH, nb+(size_t)2*HH,
                               ng,nb, linW,linB, out);
}

// round 16
// speedup vs baseline: 1.4391x; 1.4391x over previous
#include <cuda_runtime.h>
#include <math.h>

#define NN 100000
#define EE 1000000
#define FIN 500
#define HH 64
#define HB 128
#define CC 3
#define EPS_MSG 1e-7f
#define LN_EPS  1e-5f

typedef unsigned int u32;

// ---------------- device scratch ----------------
static __device__ float g_h  [(size_t)NN*HH];
static __device__ float g_tmp[(size_t)NN*HH];
static __device__ int   g_rowptr[NN+1];
static __device__ int   g_fill[NN];
static __device__ int   g_scan[NN];
static __device__ int   g_esrc[EE];
static __device__ int   g_bsums[128];
static __device__ int   g_is64;
// pre-scattered B fragments, rna-rounded tf32
static __device__ u32   g_encBf[32256];
static __device__ u32   g_W1f[3*8192];
static __device__ u32   g_W2f[3*8192];

// ---------------- helpers ----------------
__device__ __forceinline__ u32 tf32_rna(float f){
  u32 u; asm("cvt.rna.tf32.f32 %0, %1;" : "=r"(u) : "f"(f)); return u;
}
__device__ __forceinline__ void mma8(float* d, u32 a0,u32 a1,u32 a2,u32 a3,u32 b0,u32 b1){
  asm volatile("mma.sync.aligned.m16n8k8.row.col.f32.tf32.tf32.f32 "
   "{%0,%1,%2,%3},{%4,%5,%6,%7},{%8,%9},{%0,%1,%2,%3};"
   : "+f"(d[0]),"+f"(d[1]),"+f"(d[2]),"+f"(d[3])
   : "r"(a0),"r"(a1),"r"(a2),"r"(a3),"r"(b0),"r"(b1));
}
__device__ __forceinline__ u32 smem_u32(const void* p){
  u32 a; asm("{ .reg .u64 t; cvta.to.shared.u64 t, %1; cvt.u32.u64 %0, t; }" : "=r"(a) : "l"(p)); return a;
}
__device__ __forceinline__ void cp16(u32 dst, const void* src, int bytes){
  asm volatile("cp.async.ca.shared.global [%0], [%1], 16, %2;"
    :: "r"(dst), "l"(src), "r"(bytes) : "memory");
}

// 2-chain step: acc += (Ahi + Alo) * B
#define SPLIT_A(f0,f1,f2,f3) \
  u32 ah0=tf32_rna(f0), ah1=tf32_rna(f1), ah2=tf32_rna(f2), ah3=tf32_rna(f3); \
  u32 al0=__float_as_uint((f0)-__uint_as_float(ah0)); \
  u32 al1=__float_as_uint((f1)-__uint_as_float(ah1)); \
  u32 al2=__float_as_uint((f2)-__uint_as_float(ah2)); \
  u32 al3=__float_as_uint((f3)-__uint_as_float(ah3));

// ---------------- edge dtype detection / CSR ----------------
__global__ void k_detect(const void* ei){
  if(blockIdx.x==0 && threadIdx.x==0){
    const long long* p=(const long long*)ei;
    int ok=1;
    #pragma unroll
    for(int i=0;i<8;i++){ long long v=p[i]; if(v<0||v>=NN) ok=0; }
    g_is64=ok;
  }
}
__device__ __forceinline__ int edge_src(const void* ei,int e){
  return g_is64 ? (int)((const long long*)ei)[e] : ((const int*)ei)[e];
}
__device__ __forceinline__ int edge_dst(const void* ei,int e){
  return g_is64 ? (int)((const long long*)ei)[EE+e] : ((const int*)ei)[EE+e];
}
__global__ void k_zero(){
  int i=blockIdx.x*blockDim.x+threadIdx.x;
  if(i<NN) g_fill[i]=0;
}
__global__ void k_hist(const void* ei){
  int e=blockIdx.x*blockDim.x+threadIdx.x;
  if(e>=EE) return;
  atomicAdd(&g_fill[edge_dst(ei,e)],1);
}
__device__ __forceinline__ int block_incl_scan(int v){
  int lane=threadIdx.x&31, wid=threadIdx.x>>5;
  int x=v;
  #pragma unroll
  for(int o=1;o<32;o<<=1){ int y=__shfl_up_sync(0xffffffffu,x,o); if(lane>=o) x+=y; }
  __shared__ int ws[32];
  if(lane==31) ws[wid]=x;
  __syncthreads();
  int nw=(blockDim.x+31)>>5;
  if(wid==0){
    int y=(lane<nw)? ws[lane]:0;
    #pragma unroll
    for(int o=1;o<32;o<<=1){ int z=__shfl_up_sync(0xffffffffu,y,o); if(lane>=o) y+=z; }
    ws[lane]=y;
  }
  __syncthreads();
  return x + (wid>0? ws[wid-1]:0);
}
__global__ void k_scan1(){
  int i=blockIdx.x*1024+threadIdx.x;
  int v=(i<NN)? g_fill[i]:0;
  int incl=block_incl_scan(v);
  if(i<NN) g_scan[i]=incl;
  if(threadIdx.x==1023) g_bsums[blockIdx.x]=incl;
}
__global__ void k_scan2(){
  int t=threadIdx.x;
  int v=(t<98)? g_bsums[t]:0;
  int incl=block_incl_scan(v);
  if(t<98) g_bsums[t]=incl-v;
}
__global__ void k_scan3(){
  int i=blockIdx.x*blockDim.x+threadIdx.x;
  if(i>=NN) return;
  int c=g_fill[i];
  int incl=g_scan[i]+g_bsums[i>>10];
  g_rowptr[i+1]=incl;
  g_fill[i]=incl-c;
  if(i==0) g_rowptr[0]=0;
}
__global__ void k_scatter(const void* ei){
  int e=blockIdx.x*blockDim.x+threadIdx.x;
  if(e>=EE) return;
  int s=edge_src(ei,e);
  int d=edge_dst(ei,e);
  int pos=atomicAdd(&g_fill[d],1);
  g_esrc[pos]=s;
}

// ---------------- B-fragment prep (rna single block) ----------------
__global__ void k_prep(const float* __restrict__ encW,
                       const float* __restrict__ W1,
                       const float* __restrict__ W2){
  int idx=blockIdx.x*blockDim.x+threadIdx.x;
  if(idx<32256){                 // enc: 504 k x 64 n, NB=8
    int k=idx>>6, n=idx&63;
    float v=(k<FIN)? encW[(size_t)k*HH+n] : 0.f;
    int kb=k>>3, kw=k&7;
    g_encBf[(((kb*8)+(n>>3))*32 + ((n&7)*4+(kw&3)))*2 + (kw>>2)]=tf32_rna(v);
  }else if(idx<32256+3*8192){    // W1: 64 k x 128 n, NB=16
    int j=idx-32256;
    int l=j>>13, e=j&8191;
    int k=e>>7, n=e&127;
    float v=W1[(size_t)l*64*128 + (size_t)k*HB + n];
    int kb=k>>3, kw=k&7;
    g_W1f[l*8192 + (((kb*16)+(n>>3))*32 + ((n&7)*4+(kw&3)))*2 + (kw>>2)]=tf32_rna(v);
  }else if(idx<32256+6*8192){    // W2: 128 k x 64 n, NB=8
    int j=idx-32256-3*8192;
    int l=j>>13, e=j&8191;
    int k=e>>6, n=e&63;
    float v=W2[(size_t)l*128*64 + (size_t)k*HH + n];
    int kb=k>>3, kw=k&7;
    g_W2f[l*8192 + (((kb*8)+(n>>3))*32 + ((n&7)*4+(kw&3)))*2 + (kw>>2)]=tf32_rna(v);
  }
}

// ---------------- encoder GEMM: cp.async double-buffered, 2-chain (R11/R13 proven) ----------------
#define EPITCH 36
__global__ void __launch_bounds__(256) k_enc(const float* __restrict__ x,
                                             const float* __restrict__ bias){
  __shared__ float sbuf[2][128*EPITCH];
  const int tid=threadIdx.x, lane=tid&31, wid=tid>>5;
  const int g=lane>>2, qc=lane&3;
  const int r0=blockIdx.x*128 + wid*16 + g;
  float acc[8][4];
  #pragma unroll
  for(int nb=0;nb<8;nb++)
    #pragma unroll
    for(int j=0;j<4;j++) acc[nb][j]=0.f;

  const u32 sb0=smem_u32(&sbuf[0][0]);
  const u32 sb1=smem_u32(&sbuf[1][0]);
  const uint2* bp=((const uint2*)g_encBf)+lane;

  #define ISSUE(c) do{ \
    u32 dbase=((c)&1)? sb1:sb0; \
    _Pragma("unroll") \
    for(int rep=0;rep<4;rep++){ \
      int idx=tid+rep*256; \
      int row=idx>>3, seg=idx&7; \
      int gr=min(blockIdx.x*128+row, NN-1); \
      int kk=(c)*32+seg*4; \
      int kkc=min(kk,FIN-4); \
      int rem=(FIN-kk)*4; \
      int bytes=rem>=16?16:(rem>0?rem:0); \
      cp16(dbase+(u32)(row*EPITCH+seg*4)*4u, x+(size_t)gr*FIN+kkc, bytes); \
    } \
    asm volatile("cp.async.commit_group;":::"memory"); \
  }while(0)

  ISSUE(0);
  for(int c=0;c<16;c++){
    if(c<15){
      ISSUE(c+1);
      asm volatile("cp.async.wait_group 1;":::"memory");
    }else{
      asm volatile("cp.async.wait_group 0;":::"memory");
    }
    __syncthreads();
    const float* sb=((c&1)? &sbuf[1][0] : &sbuf[0][0]);
    const int ra=(wid*16+g)*EPITCH, rb=(wid*16+g+8)*EPITCH;
    #pragma unroll
    for(int s=0;s<4;s++){
      int k0=s*8+qc;
      float f0=sb[ra+k0];
      float f1=sb[rb+k0];
      float f2=sb[ra+k0+4];
      float f3=sb[rb+k0+4];
      SPLIT_A(f0,f1,f2,f3)
      const uint2* bk=bp+(size_t)(c*4+s)*8*32;
      #pragma unroll
      for(int nb=0;nb<8;nb++){
        uint2 bh=__ldg(bk+nb*32);
        mma8(acc[nb],ah0,ah1,ah2,ah3,bh.x,bh.y);
        mma8(acc[nb],al0,al1,al2,al3,bh.x,bh.y);
      }
    }
    __syncthreads();
  }
  #pragma unroll
  for(int nb=0;nb<8;nb++){
    int col=nb*8+qc*2;
    float b0v=__ldg(bias+col), b1v=__ldg(bias+col+1);
    if(r0<NN)   *(float2*)(g_h+(size_t)r0*HH+col)    =make_float2(acc[nb][0]+b0v,acc[nb][1]+b1v);
    if(r0+8<NN) *(float2*)(g_h+(size_t)(r0+8)*HH+col)=make_float2(acc[nb][2]+b0v,acc[nb][3]+b1v);
  }
}

// ---------------- fused MLP (cp.async A stage + gemm1 + LN -> smem -> gemm2) ----------------
// MODE 0: g_h = gemm2+b2 ; MODE 1: g_h += relu(LN(gemm2+b2))
// MODE 2: MODE1 epilogue + final head: out = relu(LN(hnew, fng,fnb)) @ linW + linB (g_h not written)
#define SPITCH 132
#define APITCH 68
template<int MODE>
__global__ void __launch_bounds__(256) k_mlp(int boff,
                       const float* __restrict__ b1v,
                       const float* __restrict__ g1v,
                       const float* __restrict__ be1v,
                       const float* __restrict__ b2v,
                       const float* __restrict__ gmav,
                       const float* __restrict__ betv,
                       const float* __restrict__ fng,
                       const float* __restrict__ fnb,
                       const float* __restrict__ linW,
                       const float* __restrict__ linB,
                       float* __restrict__ out){
  extern __shared__ float sh[];
  const int tid=threadIdx.x, lane=tid&31, wid=tid>>5;
  const int g=lane>>2, qc=lane&3;
  const int lr0=wid*16+g;
  const int r0=blockIdx.x*128 + lr0;

  // stage A tile (128 x 64) into smem, coalesced
  {
    const u32 sa=smem_u32(sh);
    #pragma unroll
    for(int rep=0;rep<8;rep++){
      int idx=tid+rep*256;
      int row=idx>>4, seg=idx&15;
      int gr=min(blockIdx.x*128+row, NN-1);
      cp16(sa+(u32)(row*APITCH+seg*4)*4u, g_tmp+(size_t)gr*HH+seg*4, 16);
    }
    asm volatile("cp.async.commit_group;":::"memory");
    asm volatile("cp.async.wait_group 0;":::"memory");
  }
  __syncthreads();

  // ---- gemm1 ----
  float h1acc[16][4];
  {
    #pragma unroll
    for(int nb=0;nb<16;nb++)
      #pragma unroll
      for(int j=0;j<4;j++) h1acc[nb][j]=0.f;
    const uint2* bp=((const uint2*)(g_W1f+boff))+lane;
    const int ra=lr0*APITCH, rb=(lr0+8)*APITCH;
    #pragma unroll
    for(int kb=0;kb<8;kb++){
      int k0=kb*8+qc;
      float f0=sh[ra+k0];
      float f1=sh[rb+k0];
      float f2=sh[ra+k0+4];
      float f3=sh[rb+k0+4];
      SPLIT_A(f0,f1,f2,f3)
      const uint2* bk=bp+(size_t)kb*16*32;
      #pragma unroll
      for(int nb=0;nb<16;nb++){
        uint2 bh=__ldg(bk+nb*32);
        mma8(h1acc[nb],ah0,ah1,ah2,ah3,bh.x,bh.y);
        mma8(h1acc[nb],al0,al1,al2,al3,bh.x,bh.y);
      }
    }
  }
  __syncthreads();

  {
    float s0=0.f,ss0=0.f,s1=0.f,ss1=0.f;
    #pragma unroll
    for(int nb=0;nb<16;nb++){
      int col=nb*8+qc*2;
      float c0=__ldg(b1v+col), c1=__ldg(b1v+col+1);
      h1acc[nb][0]+=c0; h1acc[nb][1]+=c1; h1acc[nb][2]+=c0; h1acc[nb][3]+=c1;
      s0+=h1acc[nb][0]+h1acc[nb][1]; ss0+=h1acc[nb][0]*h1acc[nb][0]+h1acc[nb][1]*h1acc[nb][1];
      s1+=h1acc[nb][2]+h1acc[nb][3]; ss1+=h1acc[nb][2]*h1acc[nb][2]+h1acc[nb][3]*h1acc[nb][3];
    }
    #pragma unroll
    for(int o=1;o<4;o<<=1){
      s0 +=__shfl_xor_sync(0xffffffffu,s0 ,o);
      ss0+=__shfl_xor_sync(0xffffffffu,ss0,o);
      s1 +=__shfl_xor_sync(0xffffffffu,s1 ,o);
      ss1+=__shfl_xor_sync(0xffffffffu,ss1,o);
    }
    float mu0=s0*(1.f/128.f), mu1=s1*(1.f/128.f);
    float rs0=rsqrtf(ss0*(1.f/128.f)-mu0*mu0+LN_EPS);
    float rs1=rsqrtf(ss1*(1.f/128.f)-mu1*mu1+LN_EPS);
    #pragma unroll
    for(int nb=0;nb<16;nb++){
      int col=nb*8+qc*2;
      float gv0=__ldg(g1v+col), gv1=__ldg(g1v+col+1);
      float ev0=__ldg(be1v+col), ev1=__ldg(be1v+col+1);
      sh[lr0*SPITCH+col  ]   =fmaxf((h1acc[nb][0]-mu0)*rs0*gv0+ev0,0.f);
      sh[lr0*SPITCH+col+1]   =fmaxf((h1acc[nb][1]-mu0)*rs0*gv1+ev1,0.f);
      sh[(lr0+8)*SPITCH+col  ]=fmaxf((h1acc[nb][2]-mu1)*rs1*gv0+ev0,0.f);
      sh[(lr0+8)*SPITCH+col+1]=fmaxf((h1acc[nb][3]-mu1)*rs1*gv1+ev1,0.f);
    }
  }
  __syncwarp();

  // ---- gemm2 ----
  float acc[8][4];
  #pragma unroll
  for(int nb=0;nb<8;nb++)
    #pragma unroll
    for(int j=0;j<4;j++) acc[nb][j]=0.f;
  const uint2* bp2=((const uint2*)(g_W2f+boff))+lane;
  #pragma unroll
  for(int kb=0;kb<16;kb++){
    int k0=kb*8+qc;
    float f0=sh[lr0*SPITCH+k0];
    float f1=sh[(lr0+8)*SPITCH+k0];
    float f2=sh[lr0*SPITCH+k0+4];
    float f3=sh[(lr0+8)*SPITCH+k0+4];
    SPLIT_A(f0,f1,f2,f3)
    const uint2* bk=bp2+(size_t)kb*8*32;
    #pragma unroll
    for(int nb=0;nb<8;nb++){
      uint2 bh=__ldg(bk+nb*32);
      mma8(acc[nb],ah0,ah1,ah2,ah3,bh.x,bh.y);
      mma8(acc[nb],al0,al1,al2,al3,bh.x,bh.y);
    }
  }

  if(MODE==0){
    #pragma unroll
    for(int nb=0;nb<8;nb++){
      int col=nb*8+qc*2;
      float c0=__ldg(b2v+col), c1=__ldg(b2v+col+1);
      if(r0<NN)   *(float2*)(g_h+(size_t)r0*HH+col)    =make_float2(acc[nb][0]+c0,acc[nb][1]+c1);
      if(r0+8<NN) *(float2*)(g_h+(size_t)(r0+8)*HH+col)=make_float2(acc[nb][2]+c0,acc[nb][3]+c1);
    }
  }else{
    float s0=0.f,ss0=0.f,s1=0.f,ss1=0.f;
    #pragma unroll
    for(int nb=0;nb<8;nb++){
      int col=nb*8+qc*2;
      float c0=__ldg(b2v+col), c1=__ldg(b2v+col+1);
      acc[nb][0]+=c0; acc[nb][1]+=c1; acc[nb][2]+=c0; acc[nb][3]+=c1;
      s0+=acc[nb][0]+acc[nb][1]; ss0+=acc[nb][0]*acc[nb][0]+acc[nb][1]*acc[nb][1];
      s1+=acc[nb][2]+acc[nb][3]; ss1+=acc[nb][2]*acc[nb][2]+acc[nb][3]*acc[nb][3];
    }
    #pragma unroll
    for(int o=1;o<4;o<<=1){
      s0 +=__shfl_xor_sync(0xffffffffu,s0 ,o);
      ss0+=__shfl_xor_sync(0xffffffffu,ss0,o);
      s1 +=__shfl_xor_sync(0xffffffffu,s1 ,o);
      ss1+=__shfl_xor_sync(0xffffffffu,ss1,o);
    }
    float mu0=s0*(1.f/64.f), mu1=s1*(1.f/64.f);
    float rs0=rsqrtf(ss0*(1.f/64.f)-mu0*mu0+LN_EPS);
    float rs1=rsqrtf(ss1*(1.f/64.f)-mu1*mu1+LN_EPS);
    float fs0=0.f,fss0=0.f,fs1=0.f,fss1=0.f;
    #pragma unroll
    for(int nb=0;nb<8;nb++){
      int col=nb*8+qc*2;
      float gv0=__ldg(gmav+col), gv1=__ldg(gmav+col+1);
      float ev0=__ldg(betv+col), ev1=__ldg(betv+col+1);
      float o0=fmaxf((acc[nb][0]-mu0)*rs0*gv0+ev0,0.f);
      float o1=fmaxf((acc[nb][1]-mu0)*rs0*gv1+ev1,0.f);
      float o2=fmaxf((acc[nb][2]-mu1)*rs1*gv0+ev0,0.f);
      float o3=fmaxf((acc[nb][3]-mu1)*rs1*gv1+ev1,0.f);
      int rc0=min(r0,NN-1), rc1=min(r0+8,NN-1);
      float2 old0=*(const float2*)(g_h+(size_t)rc0*HH+col);
      float2 old1=*(const float2*)(g_h+(size_t)rc1*HH+col);
      acc[nb][0]=old0.x+o0; acc[nb][1]=old0.y+o1;
      acc[nb][2]=old1.x+o2; acc[nb][3]=old1.y+o3;
      if(MODE==1){
        if(r0<NN)   *(float2*)(g_h+(size_t)r0*HH+col)    =make_float2(acc[nb][0],acc[nb][1]);
        if(r0+8<NN) *(float2*)(g_h+(size_t)(r0+8)*HH+col)=make_float2(acc[nb][2],acc[nb][3]);
      }else{
        fs0+=acc[nb][0]+acc[nb][1]; fss0+=acc[nb][0]*acc[nb][0]+acc[nb][1]*acc[nb][1];
        fs1+=acc[nb][2]+acc[nb][3]; fss1+=acc[nb][2]*acc[nb][2]+acc[nb][3]*acc[nb][3];
      }
    }
    if(MODE==2){
      #pragma unroll
      for(int o=1;o<4;o<<=1){
        fs0 +=__shfl_xor_sync(0xffffffffu,fs0 ,o);
        fss0+=__shfl_xor_sync(0xffffffffu,fss0,o);
        fs1 +=__shfl_xor_sync(0xffffffffu,fs1 ,o);
        fss1+=__shfl_xor_sync(0xffffffffu,fss1,o);
      }
      float fmu0=fs0*(1.f/64.f), fmu1=fs1*(1.f/64.f);
      float frs0=rsqrtf(fss0*(1.f/64.f)-fmu0*fmu0+LN_EPS);
      float frs1=rsqrtf(fss1*(1.f/64.f)-fmu1*fmu1+LN_EPS);
      float p00=0.f,p01=0.f,p02=0.f,p10=0.f,p11=0.f,p12=0.f;
      #pragma unroll
      for(int nb=0;nb<8;nb++){
        int col=nb*8+qc*2;
        float n0=__ldg(fng+col), n1=__ldg(fng+col+1);
        float e0=__ldg(fnb+col), e1=__ldg(fnb+col+1);
        float r00=fmaxf((acc[nb][0]-fmu0)*frs0*n0+e0,0.f);
        float r01=fmaxf((acc[nb][1]-fmu0)*frs0*n1+e1,0.f);
        float r10=fmaxf((acc[nb][2]-fmu1)*frs1*n0+e0,0.f);
        float r11=fmaxf((acc[nb][3]-fmu1)*frs1*n1+e1,0.f);
        float w00=__ldg(linW+col*CC+0), w01=__ldg(linW+col*CC+1), w02=__ldg(linW+col*CC+2);
        float w10=__ldg(linW+(col+1)*CC+0), w11=__ldg(linW+(col+1)*CC+1), w12=__ldg(linW+(col+1)*CC+2);
        p00+=r00*w00+r01*w10; p01+=r00*w01+r01*w11; p02+=r00*w02+r01*w12;
        p10+=r10*w00+r11*w10; p11+=r10*w01+r11*w11; p12+=r10*w02+r11*w12;
      }
      #pragma unroll
      for(int o=1;o<4;o<<=1){
        p00+=__shfl_xor_sync(0xffffffffu,p00,o);
        p01+=__shfl_xor_sync(0xffffffffu,p01,o);
        p02+=__shfl_xor_sync(0xffffffffu,p02,o);
        p10+=__shfl_xor_sync(0xffffffffu,p10,o);
        p11+=__shfl_xor_sync(0xffffffffu,p11,o);
        p12+=__shfl_xor_sync(0xffffffffu,p12,o);
      }
      if(qc==0){
        float lb0=__ldg(linB+0), lb1=__ldg(linB+1), lb2=__ldg(linB+2);
        if(r0<NN){
          out[(size_t)r0*CC+0]=p00+lb0;
          out[(size_t)r0*CC+1]=p01+lb1;
          out[(size_t)r0*CC+2]=p02+lb2;
        }
        if(r0+8<NN){
          out[(size_t)(r0+8)*CC+0]=p10+lb0;
          out[(size_t)(r0+8)*CC+1]=p11+lb1;
          out[(size_t)(r0+8)*CC+2]=p12+lb2;
        }
      }
    }
  }
}

// ---------------- softmax aggregation: single pass (values bounded) ----------------
__global__ void k_agg(const float* __restrict__ tptr){
  int gw=(blockIdx.x*blockDim.x+threadIdx.x)>>5;
  if(gw>=NN) return;
  int lane=threadIdx.x&31;
  float tv=*tptr;
  int s0=g_rowptr[gw], s1=g_rowptr[gw+1];
  float den0=0.f,den1=0.f,num0=0.f,num1=0.f;
  for(int base=s0;base<s1;base+=32){
    int cnt=min(32,s1-base);
    int idx=(base+lane<s1)? g_esrc[base+lane]:0;
    for(int j=0;j<cnt;j++){
      int s=__shfl_sync(0xffffffffu,idx,j);
      float2 v=*(const float2*)(g_h+(size_t)s*HH+2*lane);
      float m0=fmaxf(v.x,0.f)+EPS_MSG;
      float m1=fmaxf(v.y,0.f)+EPS_MSG;
      float a0=__expf(m0*tv);
      float a1=__expf(m1*tv);
      den0+=a0; den1+=a1;
      num0=fmaf(m0,a0,num0);
      num1=fmaf(m1,a1,num1);
    }
  }
  float2 hv=*(const float2*)(g_h+(size_t)gw*HH+2*lane);
  float o0=(s1>s0)? num0/den0:0.f;
  float o1=(s1>s0)? num1/den1:0.f;
  float2 o; o.x=o0+hv.x; o.y=o1+hv.y;
  *(float2*)(g_tmp+(size_t)gw*HH+2*lane)=o;
}

// ---------------- launch ----------------
extern "C" void kernel_launch(void* const* d_in, const int* in_sizes, int n_in,
                              void* d_out, int out_size){
  const float* x    =(const float*)d_in[0];
  const void * ei   =              d_in[1];
  const float* encW =(const float*)d_in[2];
  const float* encB =(const float*)d_in[3];
  const float* W1   =(const float*)d_in[4];
  const float* b1   =(const float*)d_in[5];
  const float* g1   =(const float*)d_in[6];
  const float* be1  =(const float*)d_in[7];
  const float* W2   =(const float*)d_in[8];
  const float* b2   =(const float*)d_in[9];
  const float* t    =(const float*)d_in[10];
  const float* ng   =(const float*)d_in[11];
  const float* nb   =(const float*)d_in[12];
  const float* linW =(const float*)d_in[13];
  const float* linB =(const float*)d_in[14];
  float* out=(float*)d_out;

  const int G=(NN+127)/128;        // 782
  const int warpBlocks=(NN*32+255)/256;
  const int SM_MLP=128*SPITCH*4;   // 67584 B

  cudaFuncSetAttribute(k_mlp<0>, cudaFuncAttributeMaxDynamicSharedMemorySize, SM_MLP);
  cudaFuncSetAttribute(k_mlp<1>, cudaFuncAttributeMaxDynamicSharedMemorySize, SM_MLP);
  cudaFuncSetAttribute(k_mlp<2>, cudaFuncAttributeMaxDynamicSharedMemorySize, SM_MLP);

  k_prep  <<<(32256+6*8192+255)/256,256>>>(encW,W1,W2);        // 0
  k_detect<<<1,32>>>(ei);                                      // 1
  k_zero  <<<(NN+255)/256,256>>>();                            // 2
  k_enc   <<<G,256>>>(x,encB);                                 // 3: profiled slot
  k_hist  <<<(EE+511)/512,512>>>(ei);
  k_scan1 <<<98,1024>>>();
  k_scan2 <<<1,128>>>();
  k_scan3 <<<(NN+255)/256,256>>>();
  k_scatter<<<(EE+511)/512,512>>>(ei);

  // pre-loop conv with layer-0 params
  k_agg <<<warpBlocks,256>>>(t+0);
  k_mlp<0><<<G,256,SM_MLP>>>(0, b1, g1, be1, b2, ng, nb, ng, nb, linW, linB, out);

  // residual layers 0,1
  for(int l=0;l<2;l++){
    k_agg <<<warpBlocks,256>>>(t+l);
    k_mlp<1><<<G,256,SM_MLP>>>(l*8192,
                               b1+(size_t)l*HB, g1+(size_t)l*HB, be1+(size_t)l*HB,
                               b2+(size_t)l*HH, ng+(size_t)l*HH, nb+(size_t)l*HH,
                               ng, nb, linW, linB, out);
  }
  // residual layer 2 with fused final head (uses ng[0],nb[0] for the last LN)
  k_agg <<<warpBlocks,256>>>(t+2);
  k_mlp<2><<<G,256,SM_MLP>>>(2*8192,
                             b1+(size_t)2*HB, g1+(size_t)2*HB, be1+(size_t)2*HB,
                             b2+(size_t)2*HH, ng+(size_t)2*HH, nb+(size_t)2*HH,
                             ng, nb, linW, linB, out);
}